// round 15
// baseline (speedup 1.0000x reference)
#include <cuda_runtime.h>
#include <cuda_bf16.h>
#include <cuda_fp16.h>

// ---------------------------------------------------------------------------
// VQVAE forward. Encoder + VQ replicate XLA-CPU (Eigen) fp32 rounding order
// bit-for-bit (argmin must match). Decoder is free-order.
// R15: d1 stored as packed fp16 pairs (half the traffic); deconv1 epilogue
// packs, deconv2 staging unpacks. Compute loops unchanged from R14.
// ---------------------------------------------------------------------------

#define BATCH 32
#define HID   128
#define EDIM  64
#define KCODES 512

typedef unsigned long long ull;

// scratch (device globals; no allocation allowed)
__device__ float g_h1[(size_t)BATCH * HID * 128 * 128];     // 268 MB
__device__ float g_z [(size_t)BATCH * EDIM * 64 * 64];      // 33.5 MB
__device__ unsigned g_zqc[(size_t)BATCH * EDIM * 64 * 64];  // fp16 dup in u32
__device__ unsigned g_d1h[(size_t)BATCH * 4 * HID * 64 * 32]; // 134 MB fp16x2 [b][p][co][mh][mw/2]
__device__ float g_wT2[16 * 128 * 64];                      // conv2 w: [tap][ci][co]
__device__ __half g_w1h[4 * 128 * 256];                     // dec_w1 fp16: [p][co][k]
__device__ float g_wr2[128 * 4 * 3 * 4];                    // dec_w2: [ci][p][co][tap4]
__device__ float g_cn[KCODES];                              // ||code||^2 (ref rounding)

// ---------------------------------------------------------------------------
// helpers
// ---------------------------------------------------------------------------
__device__ __forceinline__ unsigned smem_u32(const void* p) {
    unsigned a;
    asm("{ .reg .u64 t; cvta.to.shared.u64 t, %1; cvt.u32.u64 %0, t; }"
        : "=r"(a) : "l"(p));
    return a;
}
__device__ __forceinline__ ull pk2(float f) {
    ull d; unsigned u = __float_as_uint(f);
    asm("mov.b64 %0, {%1, %1};" : "=l"(d) : "r"(u));
    return d;
}
__device__ __forceinline__ ull pk2ab(float lo, float hi) {
    ull d;
    asm("mov.b64 %0, {%1, %2};" : "=l"(d)
        : "r"(__float_as_uint(lo)), "r"(__float_as_uint(hi)));
    return d;
}
__device__ __forceinline__ void fma2(ull& acc, ull a, ull b) {
    asm("fma.rn.f32x2 %0, %1, %2, %0;" : "+l"(acc) : "l"(a), "l"(b));
}
__device__ __forceinline__ void lds2(ull& a, ull& b, unsigned addr) {
    asm("ld.shared.v2.b64 {%0, %1}, [%2];" : "=l"(a), "=l"(b) : "r"(addr));
}
__device__ __forceinline__ void upk2(float& lo, float& hi, ull v) {
    unsigned l, h;
    asm("mov.b64 {%0, %1}, %2;" : "=r"(l), "=r"(h) : "l"(v));
    lo = __uint_as_float(l); hi = __uint_as_float(h);
}
__device__ __forceinline__ unsigned prmt(unsigned a, unsigned b, unsigned sel) {
    unsigned d;
    asm("prmt.b32 %0, %1, %2, %3;" : "=r"(d) : "r"(a), "r"(b), "r"(sel));
    return d;
}
__device__ __forceinline__ unsigned packh2(float a, float b) {
    __half2 h = __floats2half2_rn(a, b);       // .x = a -> low half
    return *(unsigned*)&h;
}

// ---------------------------------------------------------------------------
// prep: codebook norms (XLA reduce order), conv2 weight transpose, deconv1
// fp16 weights [p][co][k=ci*4+tap], deconv2 parity weights.
// ---------------------------------------------------------------------------
__global__ void prep_k(const float* __restrict__ cb,
                       const float* __restrict__ ew2,
                       const float* __restrict__ dw1,
                       const float* __restrict__ dw2) {
    int t = blockIdx.x * blockDim.x + threadIdx.x;
    int stride = gridDim.x * blockDim.x;
    if (t < KCODES) {
        float s = 0.f;
        for (int d = 0; d < EDIM; d++) {
            float v = cb[t * EDIM + d];
            s = __fadd_rn(s, __fmul_rn(v, v));
        }
        g_cn[t] = s;
    }
    for (int e = t; e < 16 * 128 * 64; e += stride) {
        int tap = e >> 13;
        int ci  = (e >> 6) & 127;
        int co  = e & 63;
        g_wT2[e] = ew2[(size_t)co * 2048 + ci * 16 + tap];
    }
    // deconv1 fp16: k = ci*4 + tap, tap = jh*2+jw -> weight elem
    // (ph+2jh, pw+2jw) for parity p = ph*2+pw.
    for (int e = t; e < 4 * 128 * 256; e += stride) {
        int k  = e & 255;
        int co = (e >> 8) & 127;
        int p  = e >> 15;
        int ci = k >> 2, tap = k & 3;
        int ph = p >> 1, pw = p & 1;
        int jh = tap >> 1, jw = tap & 1;
        float w = dw1[((size_t)co * 64 + ci) * 16 + (ph + 2 * jh) * 4 + (pw + 2 * jw)];
        g_w1h[e] = __float2half(w);
    }
    for (int e = t; e < 128 * 4 * 3; e += stride) {
        int ci  = e / 12;
        int rem = e % 12;
        int p   = rem / 3;
        int co  = rem % 3;
        int ph = p >> 1, pw = p & 1;
        const float* src = dw2 + ((size_t)co * 128 + ci) * 16;
        float* dst = g_wr2 + (size_t)e * 4;
        dst[0] = src[ ph      * 4 +  pw     ];
        dst[1] = src[ ph      * 4 + (pw + 2)];
        dst[2] = src[(ph + 2) * 4 +  pw     ];
        dst[3] = src[(ph + 2) * 4 + (pw + 2)];
    }
}

// ---------------------------------------------------------------------------
// conv1 (FFMA2, unchanged)
// ---------------------------------------------------------------------------
__global__ __launch_bounds__(256) void conv1_k(const float* __restrict__ x,
                                               const float* __restrict__ w,
                                               const float* __restrict__ bias) {
    __shared__ __align__(16) float sWT[48 * 128];
    __shared__ float sX[3 * 34 * 34];
    int b = blockIdx.z, oht = blockIdx.y, owt = blockIdx.x;
    int t = threadIdx.x;
    for (int i = t; i < 6144; i += 256) {
        int k = i >> 7, co = i & 127;
        int tap = k / 3, ci = k - tap * 3;
        sWT[i] = w[co * 48 + ci * 16 + tap];
    }
    int ih0 = oht * 32 - 1, iw0 = owt * 32 - 1;
    const float* xb = x + (size_t)b * 3 * 256 * 256;
    for (int i = t; i < 3 * 1156; i += 256) {
        int ci = i / 1156, r = (i % 1156) / 34, c = i % 34;
        int ih = ih0 + r, iw = iw0 + c;
        sX[i] = ((unsigned)ih < 256u && (unsigned)iw < 256u)
                ? xb[((size_t)ci * 256 + ih) * 256 + iw] : 0.f;
    }
    __syncthreads();
    int oh_l = t >> 4, ow_l = t & 15;
    float xw[48];
    #pragma unroll
    for (int kh = 0; kh < 4; kh++)
        #pragma unroll
        for (int kw = 0; kw < 4; kw++)
            #pragma unroll
            for (int ci = 0; ci < 3; ci++)
                xw[(kh * 4 + kw) * 3 + ci] =
                    sX[ci * 1156 + (2 * oh_l + kh) * 34 + (2 * ow_l + kw)];
    int oh = oht * 16 + oh_l, ow = owt * 16 + ow_l;
    size_t obase = (size_t)b * 2097152 + (size_t)oh * 128 + ow;
    unsigned swt = smem_u32(sWT);
    #pragma unroll 2
    for (int g = 0; g < 8; g++) {
        ull acc[8];
        #pragma unroll
        for (int j = 0; j < 8; j++) acc[j] = 0ull;
        #pragma unroll
        for (int k = 0; k < 48; k++) {
            ull X = pk2(xw[k]);
            unsigned a = swt + k * 512 + g * 64;
            ull w0, w1, w2, w3, w4, w5, w6, w7;
            lds2(w0, w1, a);
            lds2(w2, w3, a + 16);
            lds2(w4, w5, a + 32);
            lds2(w6, w7, a + 48);
            fma2(acc[0], X, w0); fma2(acc[1], X, w1);
            fma2(acc[2], X, w2); fma2(acc[3], X, w3);
            fma2(acc[4], X, w4); fma2(acc[5], X, w5);
            fma2(acc[6], X, w6); fma2(acc[7], X, w7);
        }
        #pragma unroll
        for (int j = 0; j < 8; j++) {
            int co = g * 16 + 2 * j;
            float lo, hi;
            upk2(lo, hi, acc[j]);
            float v0 = __fadd_rn(lo, __ldg(bias + co));
            float v1 = __fadd_rn(hi, __ldg(bias + co + 1));
            g_h1[obase + (size_t)co * 16384]       = fmaxf(v0, 0.f);
            g_h1[obase + (size_t)(co + 1) * 16384] = fmaxf(v1, 0.f);
        }
    }
}

// ---------------------------------------------------------------------------
// conv2 (FFMA2, 4 outputs/thread, unchanged)
// ---------------------------------------------------------------------------
__global__ __launch_bounds__(256) void conv2_k(const float* __restrict__ bias) {
    __shared__ __align__(16) float sW[8192];
    int b = blockIdx.z, oht = blockIdx.y, owt = blockIdx.x;
    int t = threadIdx.x;
    int tq = t & 3;
    int s  = t >> 2;
    int row = s >> 3;
    int cp  = s & 7;
    int oh  = oht * 8 + row;
    int ow0 = owt * 32 + cp * 4;
    const float* h1b = g_h1 + (size_t)b * 2097152;
    ull A0[8], A1[8], A2[8], A3[8];
    #pragma unroll
    for (int j = 0; j < 8; j++) { A0[j] = 0ull; A1[j] = 0ull; A2[j] = 0ull; A3[j] = 0ull; }
    unsigned swu = smem_u32(sW) + tq * 64;
    for (int tap = 0; tap < 16; tap++) {
        __syncthreads();
        {
            const float4* src = (const float4*)(g_wT2 + tap * 8192);
            float4* dst = (float4*)sW;
            #pragma unroll
            for (int i = 0; i < 8; i++) dst[t + 256 * i] = src[t + 256 * i];
        }
        __syncthreads();
        int kh = tap >> 2, kw = tap & 3;
        int ih  = 2 * oh + kh - 1;
        int iw0 = 2 * ow0 + kw - 1;
        bool hok = ((unsigned)ih < 128u);
        bool q0 = hok && ((unsigned)iw0 < 128u);
        bool q1 = hok && ((unsigned)(iw0 + 2) < 128u);
        bool q2 = hok && ((unsigned)(iw0 + 4) < 128u);
        bool q3 = hok && ((unsigned)(iw0 + 6) < 128u);
        const float* xp = h1b + (size_t)ih * 128 + iw0;
        #pragma unroll 2
        for (int ci = 0; ci < 128; ci++) {
            const float* xc = xp + (size_t)ci * 16384;
            float x0 = q0 ? __ldg(xc)     : 0.f;
            float x1 = q1 ? __ldg(xc + 2) : 0.f;
            float x2 = q2 ? __ldg(xc + 4) : 0.f;
            float x3 = q3 ? __ldg(xc + 6) : 0.f;
            ull X0 = pk2(x0), X1 = pk2(x1), X2 = pk2(x2), X3 = pk2(x3);
            unsigned a = swu + ci * 256;
            ull w0, w1, w2, w3, w4, w5, w6, w7;
            lds2(w0, w1, a);
            lds2(w2, w3, a + 16);
            lds2(w4, w5, a + 32);
            lds2(w6, w7, a + 48);
            fma2(A0[0], X0, w0); fma2(A0[1], X0, w1);
            fma2(A0[2], X0, w2); fma2(A0[3], X0, w3);
            fma2(A0[4], X0, w4); fma2(A0[5], X0, w5);
            fma2(A0[6], X0, w6); fma2(A0[7], X0, w7);
            fma2(A1[0], X1, w0); fma2(A1[1], X1, w1);
            fma2(A1[2], X1, w2); fma2(A1[3], X1, w3);
            fma2(A1[4], X1, w4); fma2(A1[5], X1, w5);
            fma2(A1[6], X1, w6); fma2(A1[7], X1, w7);
            fma2(A2[0], X2, w0); fma2(A2[1], X2, w1);
            fma2(A2[2], X2, w2); fma2(A2[3], X2, w3);
            fma2(A2[4], X2, w4); fma2(A2[5], X2, w5);
            fma2(A2[6], X2, w6); fma2(A2[7], X2, w7);
            fma2(A3[0], X3, w0); fma2(A3[1], X3, w1);
            fma2(A3[2], X3, w2); fma2(A3[3], X3, w3);
            fma2(A3[4], X3, w4); fma2(A3[5], X3, w5);
            fma2(A3[6], X3, w6); fma2(A3[7], X3, w7);
        }
    }
    size_t ob = (size_t)b * 262144 + (size_t)oh * 64 + ow0;
    #pragma unroll
    for (int j = 0; j < 8; j++) {
        int co0 = tq * 16 + 2 * j;
        float bv0 = __ldg(bias + co0), bv1 = __ldg(bias + co0 + 1);
        float lo, hi;
        size_t o0 = ob + (size_t)co0 * 4096;
        size_t o1 = ob + (size_t)(co0 + 1) * 4096;
        upk2(lo, hi, A0[j]); g_z[o0]     = __fadd_rn(lo, bv0); g_z[o1]     = __fadd_rn(hi, bv1);
        upk2(lo, hi, A1[j]); g_z[o0 + 1] = __fadd_rn(lo, bv0); g_z[o1 + 1] = __fadd_rn(hi, bv1);
        upk2(lo, hi, A2[j]); g_z[o0 + 2] = __fadd_rn(lo, bv0); g_z[o1 + 2] = __fadd_rn(hi, bv1);
        upk2(lo, hi, A3[j]); g_z[o0 + 3] = __fadd_rn(lo, bv0); g_z[o1 + 3] = __fadd_rn(hi, bv1);
    }
}

// ---------------------------------------------------------------------------
// VQ assign + z_q scatter (1 vector/thread, grid 512). Argmin arithmetic
// bit-exact (unchanged). Scatter writes z_q_st as fp16 duplicated in u32.
// ---------------------------------------------------------------------------
__global__ __launch_bounds__(256) void vq_k(const float* __restrict__ cb) {
    __shared__ __align__(16) float sC[128 * 64];  // [pair][e][2]
    __shared__ float sN[128];
    int v = blockIdx.x * 256 + threadIdx.x;
    float z[64];
    const float4* zp = (const float4*)(g_z + (size_t)v * 64);
    #pragma unroll
    for (int q = 0; q < 16; q++) {
        float4 f = zp[q];
        z[q * 4 + 0] = f.x; z[q * 4 + 1] = f.y;
        z[q * 4 + 2] = f.z; z[q * 4 + 3] = f.w;
    }
    float zz = 0.f;
    #pragma unroll
    for (int e = 0; e < 64; e++)
        zz = __fadd_rn(zz, __fmul_rn(z[e], z[e]));
    float best = 3.4e38f;
    int bi = 0;
    unsigned scu = smem_u32(sC);
    for (int ch = 0; ch < 4; ch++) {
        __syncthreads();
        const float* src = cb + (size_t)ch * 8192;
        for (int i = threadIdx.x; i < 8192; i += 256) {
            int pr = i >> 7, r = i & 127, e = r >> 1, s2 = r & 1;
            sC[i] = src[(2 * pr + s2) * 64 + e];
        }
        if (threadIdx.x < 128) sN[threadIdx.x] = g_cn[ch * 128 + threadIdx.x];
        __syncthreads();
        for (int kk = 0; kk < 128; kk += 16) {      // 8 pairs = 16 codes
            ull S[8];
            #pragma unroll
            for (int pp = 0; pp < 8; pp++) S[pp] = 0ull;
            unsigned base = scu + (kk >> 1) * 512;
            #pragma unroll
            for (int e = 0; e < 64; e += 2) {
                ull Z0 = pk2(z[e]), Z1 = pk2(z[e + 1]);
                #pragma unroll
                for (int pp = 0; pp < 8; pp++) {
                    ull w0, w1;
                    lds2(w0, w1, base + pp * 512 + e * 8);
                    fma2(S[pp], Z0, w0);
                    fma2(S[pp], Z1, w1);
                }
            }
            #pragma unroll
            for (int pp = 0; pp < 8; pp++) {
                int k0 = kk + 2 * pp;
                float s0, s1;
                upk2(s0, s1, S[pp]);
                float d0 = __fadd_rn(__fadd_rn(zz, -2.f * s0), sN[k0]);
                float d1 = __fadd_rn(__fadd_rn(zz, -2.f * s1), sN[k0 + 1]);
                if (d0 < best) { best = d0; bi = ch * 128 + k0; }
                if (d1 < best) { best = d1; bi = ch * 128 + k0 + 1; }
            }
        }
    }
    {
        const float* c = cb + (size_t)bi * 64;
        size_t base = (size_t)(v >> 12) * 262144 + (v & 4095);
        #pragma unroll 8
        for (int e = 0; e < 64; e++) {
            float zv = z[e];
            float st = __fadd_rn(zv, __fadd_rn(__ldg(c + e), -zv));
            unsigned us = (unsigned)__half_as_ushort(__float2half(st));
            g_zqc[base + (size_t)e * 4096] = us | (us << 16);
        }
    }
}

// ---------------------------------------------------------------------------
// deconv1 warp-MMA fp16 single-pass: block (mh, p, b):
// D[co=128][mw=64] = W_p . X^T, W/X fp16, f32 accum. X from packed g_zqc
// (u32 + prmt), 16 kb-steps, A loaded once per kb (depth-1 prefetch).
// Output packed fp16 pairs (mw-adjacent), parity-major, bias+relu.
// ---------------------------------------------------------------------------
extern __shared__ __align__(16) char dsm1[];
__global__ __launch_bounds__(256, 2) void deconv1_mma_k(const float* __restrict__ bias) {
    unsigned xh = smem_u32(dsm1);            // 64 * 264 * 2B = 33792
    int t = threadIdx.x;
    int mh = blockIdx.x, p = blockIdx.y, b = blockIdx.z;
    int ph = p >> 1, pw = p & 1;

    // ---- build X from packed fp16 ----
    {
        int n = t & 63, kq = t >> 6;         // thread: one n, 16 ci
        int r0 = mh - 1 + ph, c0 = n - 1 + pw;
        bool rok0 = ((unsigned)r0 < 64u), rok1 = ((unsigned)(r0 + 1) < 64u);
        bool cok0 = ((unsigned)c0 < 64u), cok1 = ((unsigned)(c0 + 1) < 64u);
        const unsigned* zb = g_zqc + (size_t)b * 262144 + (size_t)r0 * 64 + c0;
        unsigned rowoff = (unsigned)(n * 264) * 2;
        #pragma unroll 4
        for (int cc = 0; cc < 16; cc++) {
            int ci = kq * 16 + cc;
            const unsigned* zc = zb + (size_t)ci * 4096;
            unsigned w00 = (rok0 && cok0) ? __ldg(zc)      : 0u;
            unsigned w01 = (rok0 && cok1) ? __ldg(zc + 1)  : 0u;
            unsigned w10 = (rok1 && cok0) ? __ldg(zc + 64) : 0u;
            unsigned w11 = (rok1 && cok1) ? __ldg(zc + 65) : 0u;
            unsigned hp0 = prmt(w00, w01, 0x5410u);
            unsigned hp1 = prmt(w10, w11, 0x5410u);
            unsigned off = rowoff + (unsigned)(ci * 4) * 2;
            asm volatile("st.shared.b32 [%0], %1;" :: "r"(xh + off),     "r"(hp0) : "memory");
            asm volatile("st.shared.b32 [%0], %1;" :: "r"(xh + off + 4), "r"(hp1) : "memory");
        }
    }
    __syncthreads();

    // ---- warp MMA ----
    int wid = t >> 5, lane = t & 31;
    int g = lane >> 2, q4 = lane & 3;
    int m0 = (wid >> 1) * 32, n0 = (wid & 1) * 32;
    const __half* wh = g_w1h + (size_t)p * 32768;

    float c[2][4][4];
    #pragma unroll
    for (int mt = 0; mt < 2; mt++)
        #pragma unroll
        for (int nt = 0; nt < 4; nt++)
            #pragma unroll
            for (int j = 0; j < 4; j++) c[mt][nt][j] = 0.f;

    unsigned ah[2][4], ahn[2][4];
    #pragma unroll
    for (int mt = 0; mt < 2; mt++) {
        const __half* w0 = wh + (size_t)(m0 + mt * 16 + g) * 256 + 2 * q4;
        ah[mt][0] = __ldg((const unsigned*)w0);
        ah[mt][1] = __ldg((const unsigned*)(w0 + 2048));
        ah[mt][2] = __ldg((const unsigned*)(w0 + 8));
        ah[mt][3] = __ldg((const unsigned*)(w0 + 2056));
    }

    for (int kb = 0; kb < 16; kb++) {
        if (kb < 15) {
            int nkb = (kb + 1) * 16;
            #pragma unroll
            for (int mt = 0; mt < 2; mt++) {
                const __half* w0 = wh + (size_t)(m0 + mt * 16 + g) * 256 + nkb + 2 * q4;
                ahn[mt][0] = __ldg((const unsigned*)w0);
                ahn[mt][1] = __ldg((const unsigned*)(w0 + 2048));
                ahn[mt][2] = __ldg((const unsigned*)(w0 + 8));
                ahn[mt][3] = __ldg((const unsigned*)(w0 + 2056));
            }
        }
        unsigned bh[4][2];
        #pragma unroll
        for (int nt = 0; nt < 4; nt++) {
            unsigned boff = (unsigned)(((n0 + nt * 8 + g) * 264) + kb * 16 + 2 * q4) * 2;
            asm volatile("ld.shared.b32 %0, [%1];" : "=r"(bh[nt][0]) : "r"(xh + boff));
            asm volatile("ld.shared.b32 %0, [%1];" : "=r"(bh[nt][1]) : "r"(xh + boff + 16));
        }
        #pragma unroll
        for (int nt = 0; nt < 4; nt++)
            #pragma unroll
            for (int mt = 0; mt < 2; mt++)
                asm volatile(
                    "mma.sync.aligned.m16n8k16.row.col.f32.f16.f16.f32 "
                    "{%0,%1,%2,%3}, {%4,%5,%6,%7}, {%8,%9}, {%0,%1,%2,%3};"
                    : "+f"(c[mt][nt][0]), "+f"(c[mt][nt][1]),
                      "+f"(c[mt][nt][2]), "+f"(c[mt][nt][3])
                    : "r"(ah[mt][0]), "r"(ah[mt][1]), "r"(ah[mt][2]), "r"(ah[mt][3]),
                      "r"(bh[nt][0]), "r"(bh[nt][1]));
        #pragma unroll
        for (int mt = 0; mt < 2; mt++)
            #pragma unroll
            for (int j = 0; j < 4; j++) ah[mt][j] = ahn[mt][j];
    }

    // ---- epilogue: bias + relu, packed fp16 parity-major store ----
    unsigned* dbase = g_d1h + ((size_t)(b * 4 + p) * 128) * 2048 + (size_t)mh * 32;
    #pragma unroll
    for (int mt = 0; mt < 2; mt++) {
        int co0 = m0 + mt * 16 + g;
        float bv0 = __ldg(bias + co0);
        float bv1 = __ldg(bias + co0 + 8);
        #pragma unroll
        for (int nt = 0; nt < 4; nt++) {
            int col = n0 + nt * 8 + 2 * q4;     // even
            unsigned u0 = packh2(fmaxf(c[mt][nt][0] + bv0, 0.f),
                                 fmaxf(c[mt][nt][1] + bv0, 0.f));
            unsigned u1 = packh2(fmaxf(c[mt][nt][2] + bv1, 0.f),
                                 fmaxf(c[mt][nt][3] + bv1, 0.f));
            dbase[(size_t)co0 * 2048 + (col >> 1)]       = u0;
            dbase[(size_t)(co0 + 8) * 2048 + (col >> 1)] = u1;
        }
    }
}

// ---------------------------------------------------------------------------
// deconv2 (FFMA2 tap-split) — reads packed-fp16 parity-major d1 layout.
// ---------------------------------------------------------------------------
__global__ __launch_bounds__(256) void deconv2_k(const float* __restrict__ bias,
                                                 float* __restrict__ out) {
    __shared__ float sX[32 * 100];
    __shared__ __align__(16) float sW[32 * 4 * 3 * 4];
    int b = blockIdx.z, oht = blockIdx.y, owt = blockIdx.x;
    int t = threadIdx.x;
    int r0 = oht * 8 - 1, c0 = owt * 8 - 1;
    int oh_l = t >> 4, ow_l = t & 15;
    int ph = oh_l & 1, pw = ow_l & 1, p = ph * 2 + pw;
    int xr = (oh_l >> 1) + ph;
    int xc = (ow_l >> 1) + pw;
    ull a0 = 0ull, a1 = 0ull, a2 = 0ull;
    unsigned swu = smem_u32(sW) + p * 48;
    for (int chn = 0; chn < 4; chn++) {
        __syncthreads();
        for (int i = t; i < 3200; i += 256) {
            int ci = i / 100, rr = (i % 100) / 10, cc = i % 10;
            int ih = r0 + rr, iw = c0 + cc;
            float v = 0.f;
            if ((unsigned)ih < 128u && (unsigned)iw < 128u) {
                int pq = (ih & 1) * 2 + (iw & 1);
                int y = ih >> 1, xcol = iw >> 1;
                unsigned us = g_d1h[((size_t)(b * 4 + pq) * 128 + (chn * 32 + ci)) * 2048
                                    + y * 32 + (xcol >> 1)];
                unsigned h = (xcol & 1) ? (us >> 16) : (us & 0xffffu);
                v = __half2float(__ushort_as_half((unsigned short)h));
            }
            sX[i] = v;
        }
        for (int i = t; i < 384; i += 256) {
            int ci = i / 12, rem = i % 12;
            ((float4*)sW)[i] =
                ((const float4*)g_wr2)[(size_t)(chn * 32 + ci) * 12 + rem];
        }
        __syncthreads();
        #pragma unroll 4
        for (int ci = 0; ci < 32; ci++) {
            int base = ci * 100;
            ull XA = pk2ab(sX[base + xr * 10 + xc], sX[base + xr * 10 + xc + 1]);
            ull XB = pk2ab(sX[base + (xr + 1) * 10 + xc],
                           sX[base + (xr + 1) * 10 + xc + 1]);
            unsigned a = swu + ci * 192;
            ull w01, w23, v01, v23, u01, u23;
            lds2(w01, w23, a);
            lds2(v01, v23, a + 16);
            lds2(u01, u23, a + 32);
            fma2(a0, XA, w01); fma2(a0, XB, w23);
            fma2(a1, XA, v01); fma2(a1, XB, v23);
            fma2(a2, XA, u01); fma2(a2, XB, u23);
        }
    }
    int oh = oht * 16 + oh_l, ow = owt * 16 + ow_l;
    size_t obase = (size_t)b * 3 * 65536 + (size_t)oh * 256 + ow;
    float lo, hi;
    upk2(lo, hi, a0); out[obase]             = (lo + hi) + __ldg(bias + 0);
    upk2(lo, hi, a1); out[obase + 65536]     = (lo + hi) + __ldg(bias + 1);
    upk2(lo, hi, a2); out[obase + 2 * 65536] = (lo + hi) + __ldg(bias + 2);
}

// ---------------------------------------------------------------------------
extern "C" void kernel_launch(void* const* d_in, const int* in_sizes, int n_in,
                              void* d_out, int out_size) {
    const float* x      = (const float*)d_in[0];
    const float* enc_w1 = (const float*)d_in[1];
    const float* enc_b1 = (const float*)d_in[2];
    const float* enc_w2 = (const float*)d_in[3];
    const float* enc_b2 = (const float*)d_in[4];
    const float* dec_w1 = (const float*)d_in[5];
    const float* dec_b1 = (const float*)d_in[6];
    const float* dec_w2 = (const float*)d_in[7];
    const float* dec_b2 = (const float*)d_in[8];
    const float* cb     = (const float*)d_in[9];
    float* out = (float*)d_out;

    prep_k<<<64, 256>>>(cb, enc_w2, dec_w1, dec_w2);
    conv1_k<<<dim3(8, 8, BATCH), 256>>>(x, enc_w1, enc_b1);
    conv2_k<<<dim3(2, 8, BATCH), 256>>>(enc_b2);
    vq_k<<<512, 256>>>(cb);
    deconv1_mma_k<<<dim3(64, 4, BATCH), 256, 33792>>>(dec_b1);
    deconv2_k<<<dim3(16, 16, BATCH), 256>>>(dec_b2, out);
}

// round 16
// speedup vs baseline: 1.0472x; 1.0472x over previous
#include <cuda_runtime.h>
#include <cuda_bf16.h>
#include <cuda_fp16.h>

// ---------------------------------------------------------------------------
// VQVAE forward. Encoder + VQ replicate XLA-CPU (Eigen) fp32 rounding order
// bit-for-bit (argmin must match). Decoder is free-order.
// R16: revert d1 to fp32 (R15's fp16 packing regressed); deconv2 restructured
// to 2 outputs/thread (ow, ow+16 share parity -> shared weights, halved
// staging + barriers). Numerics identical to R14.
// ---------------------------------------------------------------------------

#define BATCH 32
#define HID   128
#define EDIM  64
#define KCODES 512

typedef unsigned long long ull;

// scratch (device globals; no allocation allowed)
__device__ float g_h1[(size_t)BATCH * HID * 128 * 128];     // 268 MB
__device__ float g_z [(size_t)BATCH * EDIM * 64 * 64];      // 33.5 MB
__device__ unsigned g_zqc[(size_t)BATCH * EDIM * 64 * 64];  // fp16 dup in u32
__device__ float g_d1[(size_t)BATCH * 4 * HID * 64 * 64];   // 268 MB [b][p][co][mh][mw]
__device__ float g_wT2[16 * 128 * 64];                      // conv2 w: [tap][ci][co]
__device__ __half g_w1h[4 * 128 * 256];                     // dec_w1 fp16: [p][co][k]
__device__ float g_wr2[128 * 4 * 3 * 4];                    // dec_w2: [ci][p][co][tap4]
__device__ float g_cn[KCODES];                              // ||code||^2 (ref rounding)

// ---------------------------------------------------------------------------
// helpers
// ---------------------------------------------------------------------------
__device__ __forceinline__ unsigned smem_u32(const void* p) {
    unsigned a;
    asm("{ .reg .u64 t; cvta.to.shared.u64 t, %1; cvt.u32.u64 %0, t; }"
        : "=r"(a) : "l"(p));
    return a;
}
__device__ __forceinline__ ull pk2(float f) {
    ull d; unsigned u = __float_as_uint(f);
    asm("mov.b64 %0, {%1, %1};" : "=l"(d) : "r"(u));
    return d;
}
__device__ __forceinline__ ull pk2ab(float lo, float hi) {
    ull d;
    asm("mov.b64 %0, {%1, %2};" : "=l"(d)
        : "r"(__float_as_uint(lo)), "r"(__float_as_uint(hi)));
    return d;
}
__device__ __forceinline__ void fma2(ull& acc, ull a, ull b) {
    asm("fma.rn.f32x2 %0, %1, %2, %0;" : "+l"(acc) : "l"(a), "l"(b));
}
__device__ __forceinline__ void lds2(ull& a, ull& b, unsigned addr) {
    asm("ld.shared.v2.b64 {%0, %1}, [%2];" : "=l"(a), "=l"(b) : "r"(addr));
}
__device__ __forceinline__ void upk2(float& lo, float& hi, ull v) {
    unsigned l, h;
    asm("mov.b64 {%0, %1}, %2;" : "=r"(l), "=r"(h) : "l"(v));
    lo = __uint_as_float(l); hi = __uint_as_float(h);
}
__device__ __forceinline__ unsigned prmt(unsigned a, unsigned b, unsigned sel) {
    unsigned d;
    asm("prmt.b32 %0, %1, %2, %3;" : "=r"(d) : "r"(a), "r"(b), "r"(sel));
    return d;
}

// ---------------------------------------------------------------------------
// prep: codebook norms (XLA reduce order), conv2 weight transpose, deconv1
// fp16 weights [p][co][k=ci*4+tap], deconv2 parity weights.
// ---------------------------------------------------------------------------
__global__ void prep_k(const float* __restrict__ cb,
                       const float* __restrict__ ew2,
                       const float* __restrict__ dw1,
                       const float* __restrict__ dw2) {
    int t = blockIdx.x * blockDim.x + threadIdx.x;
    int stride = gridDim.x * blockDim.x;
    if (t < KCODES) {
        float s = 0.f;
        for (int d = 0; d < EDIM; d++) {
            float v = cb[t * EDIM + d];
            s = __fadd_rn(s, __fmul_rn(v, v));
        }
        g_cn[t] = s;
    }
    for (int e = t; e < 16 * 128 * 64; e += stride) {
        int tap = e >> 13;
        int ci  = (e >> 6) & 127;
        int co  = e & 63;
        g_wT2[e] = ew2[(size_t)co * 2048 + ci * 16 + tap];
    }
    // deconv1 fp16: k = ci*4 + tap, tap = jh*2+jw -> weight elem
    // (ph+2jh, pw+2jw) for parity p = ph*2+pw.
    for (int e = t; e < 4 * 128 * 256; e += stride) {
        int k  = e & 255;
        int co = (e >> 8) & 127;
        int p  = e >> 15;
        int ci = k >> 2, tap = k & 3;
        int ph = p >> 1, pw = p & 1;
        int jh = tap >> 1, jw = tap & 1;
        float w = dw1[((size_t)co * 64 + ci) * 16 + (ph + 2 * jh) * 4 + (pw + 2 * jw)];
        g_w1h[e] = __float2half(w);
    }
    for (int e = t; e < 128 * 4 * 3; e += stride) {
        int ci  = e / 12;
        int rem = e % 12;
        int p   = rem / 3;
        int co  = rem % 3;
        int ph = p >> 1, pw = p & 1;
        const float* src = dw2 + ((size_t)co * 128 + ci) * 16;
        float* dst = g_wr2 + (size_t)e * 4;
        dst[0] = src[ ph      * 4 +  pw     ];
        dst[1] = src[ ph      * 4 + (pw + 2)];
        dst[2] = src[(ph + 2) * 4 +  pw     ];
        dst[3] = src[(ph + 2) * 4 + (pw + 2)];
    }
}

// ---------------------------------------------------------------------------
// conv1 (FFMA2, unchanged)
// ---------------------------------------------------------------------------
__global__ __launch_bounds__(256) void conv1_k(const float* __restrict__ x,
                                               const float* __restrict__ w,
                                               const float* __restrict__ bias) {
    __shared__ __align__(16) float sWT[48 * 128];
    __shared__ float sX[3 * 34 * 34];
    int b = blockIdx.z, oht = blockIdx.y, owt = blockIdx.x;
    int t = threadIdx.x;
    for (int i = t; i < 6144; i += 256) {
        int k = i >> 7, co = i & 127;
        int tap = k / 3, ci = k - tap * 3;
        sWT[i] = w[co * 48 + ci * 16 + tap];
    }
    int ih0 = oht * 32 - 1, iw0 = owt * 32 - 1;
    const float* xb = x + (size_t)b * 3 * 256 * 256;
    for (int i = t; i < 3 * 1156; i += 256) {
        int ci = i / 1156, r = (i % 1156) / 34, c = i % 34;
        int ih = ih0 + r, iw = iw0 + c;
        sX[i] = ((unsigned)ih < 256u && (unsigned)iw < 256u)
                ? xb[((size_t)ci * 256 + ih) * 256 + iw] : 0.f;
    }
    __syncthreads();
    int oh_l = t >> 4, ow_l = t & 15;
    float xw[48];
    #pragma unroll
    for (int kh = 0; kh < 4; kh++)
        #pragma unroll
        for (int kw = 0; kw < 4; kw++)
            #pragma unroll
            for (int ci = 0; ci < 3; ci++)
                xw[(kh * 4 + kw) * 3 + ci] =
                    sX[ci * 1156 + (2 * oh_l + kh) * 34 + (2 * ow_l + kw)];
    int oh = oht * 16 + oh_l, ow = owt * 16 + ow_l;
    size_t obase = (size_t)b * 2097152 + (size_t)oh * 128 + ow;
    unsigned swt = smem_u32(sWT);
    #pragma unroll 2
    for (int g = 0; g < 8; g++) {
        ull acc[8];
        #pragma unroll
        for (int j = 0; j < 8; j++) acc[j] = 0ull;
        #pragma unroll
        for (int k = 0; k < 48; k++) {
            ull X = pk2(xw[k]);
            unsigned a = swt + k * 512 + g * 64;
            ull w0, w1, w2, w3, w4, w5, w6, w7;
            lds2(w0, w1, a);
            lds2(w2, w3, a + 16);
            lds2(w4, w5, a + 32);
            lds2(w6, w7, a + 48);
            fma2(acc[0], X, w0); fma2(acc[1], X, w1);
            fma2(acc[2], X, w2); fma2(acc[3], X, w3);
            fma2(acc[4], X, w4); fma2(acc[5], X, w5);
            fma2(acc[6], X, w6); fma2(acc[7], X, w7);
        }
        #pragma unroll
        for (int j = 0; j < 8; j++) {
            int co = g * 16 + 2 * j;
            float lo, hi;
            upk2(lo, hi, acc[j]);
            float v0 = __fadd_rn(lo, __ldg(bias + co));
            float v1 = __fadd_rn(hi, __ldg(bias + co + 1));
            g_h1[obase + (size_t)co * 16384]       = fmaxf(v0, 0.f);
            g_h1[obase + (size_t)(co + 1) * 16384] = fmaxf(v1, 0.f);
        }
    }
}

// ---------------------------------------------------------------------------
// conv2 (FFMA2, 4 outputs/thread, unchanged)
// ---------------------------------------------------------------------------
__global__ __launch_bounds__(256) void conv2_k(const float* __restrict__ bias) {
    __shared__ __align__(16) float sW[8192];
    int b = blockIdx.z, oht = blockIdx.y, owt = blockIdx.x;
    int t = threadIdx.x;
    int tq = t & 3;
    int s  = t >> 2;
    int row = s >> 3;
    int cp  = s & 7;
    int oh  = oht * 8 + row;
    int ow0 = owt * 32 + cp * 4;
    const float* h1b = g_h1 + (size_t)b * 2097152;
    ull A0[8], A1[8], A2[8], A3[8];
    #pragma unroll
    for (int j = 0; j < 8; j++) { A0[j] = 0ull; A1[j] = 0ull; A2[j] = 0ull; A3[j] = 0ull; }
    unsigned swu = smem_u32(sW) + tq * 64;
    for (int tap = 0; tap < 16; tap++) {
        __syncthreads();
        {
            const float4* src = (const float4*)(g_wT2 + tap * 8192);
            float4* dst = (float4*)sW;
            #pragma unroll
            for (int i = 0; i < 8; i++) dst[t + 256 * i] = src[t + 256 * i];
        }
        __syncthreads();
        int kh = tap >> 2, kw = tap & 3;
        int ih  = 2 * oh + kh - 1;
        int iw0 = 2 * ow0 + kw - 1;
        bool hok = ((unsigned)ih < 128u);
        bool q0 = hok && ((unsigned)iw0 < 128u);
        bool q1 = hok && ((unsigned)(iw0 + 2) < 128u);
        bool q2 = hok && ((unsigned)(iw0 + 4) < 128u);
        bool q3 = hok && ((unsigned)(iw0 + 6) < 128u);
        const float* xp = h1b + (size_t)ih * 128 + iw0;
        #pragma unroll 2
        for (int ci = 0; ci < 128; ci++) {
            const float* xc = xp + (size_t)ci * 16384;
            float x0 = q0 ? __ldg(xc)     : 0.f;
            float x1 = q1 ? __ldg(xc + 2) : 0.f;
            float x2 = q2 ? __ldg(xc + 4) : 0.f;
            float x3 = q3 ? __ldg(xc + 6) : 0.f;
            ull X0 = pk2(x0), X1 = pk2(x1), X2 = pk2(x2), X3 = pk2(x3);
            unsigned a = swu + ci * 256;
            ull w0, w1, w2, w3, w4, w5, w6, w7;
            lds2(w0, w1, a);
            lds2(w2, w3, a + 16);
            lds2(w4, w5, a + 32);
            lds2(w6, w7, a + 48);
            fma2(A0[0], X0, w0); fma2(A0[1], X0, w1);
            fma2(A0[2], X0, w2); fma2(A0[3], X0, w3);
            fma2(A0[4], X0, w4); fma2(A0[5], X0, w5);
            fma2(A0[6], X0, w6); fma2(A0[7], X0, w7);
            fma2(A1[0], X1, w0); fma2(A1[1], X1, w1);
            fma2(A1[2], X1, w2); fma2(A1[3], X1, w3);
            fma2(A1[4], X1, w4); fma2(A1[5], X1, w5);
            fma2(A1[6], X1, w6); fma2(A1[7], X1, w7);
            fma2(A2[0], X2, w0); fma2(A2[1], X2, w1);
            fma2(A2[2], X2, w2); fma2(A2[3], X2, w3);
            fma2(A2[4], X2, w4); fma2(A2[5], X2, w5);
            fma2(A2[6], X2, w6); fma2(A2[7], X2, w7);
            fma2(A3[0], X3, w0); fma2(A3[1], X3, w1);
            fma2(A3[2], X3, w2); fma2(A3[3], X3, w3);
            fma2(A3[4], X3, w4); fma2(A3[5], X3, w5);
            fma2(A3[6], X3, w6); fma2(A3[7], X3, w7);
        }
    }
    size_t ob = (size_t)b * 262144 + (size_t)oh * 64 + ow0;
    #pragma unroll
    for (int j = 0; j < 8; j++) {
        int co0 = tq * 16 + 2 * j;
        float bv0 = __ldg(bias + co0), bv1 = __ldg(bias + co0 + 1);
        float lo, hi;
        size_t o0 = ob + (size_t)co0 * 4096;
        size_t o1 = ob + (size_t)(co0 + 1) * 4096;
        upk2(lo, hi, A0[j]); g_z[o0]     = __fadd_rn(lo, bv0); g_z[o1]     = __fadd_rn(hi, bv1);
        upk2(lo, hi, A1[j]); g_z[o0 + 1] = __fadd_rn(lo, bv0); g_z[o1 + 1] = __fadd_rn(hi, bv1);
        upk2(lo, hi, A2[j]); g_z[o0 + 2] = __fadd_rn(lo, bv0); g_z[o1 + 2] = __fadd_rn(hi, bv1);
        upk2(lo, hi, A3[j]); g_z[o0 + 3] = __fadd_rn(lo, bv0); g_z[o1 + 3] = __fadd_rn(hi, bv1);
    }
}

// ---------------------------------------------------------------------------
// VQ assign + z_q scatter (1 vector/thread, grid 512). Argmin arithmetic
// bit-exact (unchanged). Scatter writes z_q_st as fp16 duplicated in u32.
// ---------------------------------------------------------------------------
__global__ __launch_bounds__(256) void vq_k(const float* __restrict__ cb) {
    __shared__ __align__(16) float sC[128 * 64];  // [pair][e][2]
    __shared__ float sN[128];
    int v = blockIdx.x * 256 + threadIdx.x;
    float z[64];
    const float4* zp = (const float4*)(g_z + (size_t)v * 64);
    #pragma unroll
    for (int q = 0; q < 16; q++) {
        float4 f = zp[q];
        z[q * 4 + 0] = f.x; z[q * 4 + 1] = f.y;
        z[q * 4 + 2] = f.z; z[q * 4 + 3] = f.w;
    }
    float zz = 0.f;
    #pragma unroll
    for (int e = 0; e < 64; e++)
        zz = __fadd_rn(zz, __fmul_rn(z[e], z[e]));
    float best = 3.4e38f;
    int bi = 0;
    unsigned scu = smem_u32(sC);
    for (int ch = 0; ch < 4; ch++) {
        __syncthreads();
        const float* src = cb + (size_t)ch * 8192;
        for (int i = threadIdx.x; i < 8192; i += 256) {
            int pr = i >> 7, r = i & 127, e = r >> 1, s2 = r & 1;
            sC[i] = src[(2 * pr + s2) * 64 + e];
        }
        if (threadIdx.x < 128) sN[threadIdx.x] = g_cn[ch * 128 + threadIdx.x];
        __syncthreads();
        for (int kk = 0; kk < 128; kk += 16) {      // 8 pairs = 16 codes
            ull S[8];
            #pragma unroll
            for (int pp = 0; pp < 8; pp++) S[pp] = 0ull;
            unsigned base = scu + (kk >> 1) * 512;
            #pragma unroll
            for (int e = 0; e < 64; e += 2) {
                ull Z0 = pk2(z[e]), Z1 = pk2(z[e + 1]);
                #pragma unroll
                for (int pp = 0; pp < 8; pp++) {
                    ull w0, w1;
                    lds2(w0, w1, base + pp * 512 + e * 8);
                    fma2(S[pp], Z0, w0);
                    fma2(S[pp], Z1, w1);
                }
            }
            #pragma unroll
            for (int pp = 0; pp < 8; pp++) {
                int k0 = kk + 2 * pp;
                float s0, s1;
                upk2(s0, s1, S[pp]);
                float d0 = __fadd_rn(__fadd_rn(zz, -2.f * s0), sN[k0]);
                float d1 = __fadd_rn(__fadd_rn(zz, -2.f * s1), sN[k0 + 1]);
                if (d0 < best) { best = d0; bi = ch * 128 + k0; }
                if (d1 < best) { best = d1; bi = ch * 128 + k0 + 1; }
            }
        }
    }
    {
        const float* c = cb + (size_t)bi * 64;
        size_t base = (size_t)(v >> 12) * 262144 + (v & 4095);
        #pragma unroll 8
        for (int e = 0; e < 64; e++) {
            float zv = z[e];
            float st = __fadd_rn(zv, __fadd_rn(__ldg(c + e), -zv));
            unsigned us = (unsigned)__half_as_ushort(__float2half(st));
            g_zqc[base + (size_t)e * 4096] = us | (us << 16);
        }
    }
}

// ---------------------------------------------------------------------------
// deconv1 warp-MMA fp16 single-pass (R14): block (mh, p, b):
// D[co=128][mw=64] = W_p . X^T, W/X fp16, f32 accum. X from packed g_zqc
// (u32 + prmt), 16 kb-steps, A loaded once per kb (depth-1 prefetch).
// Parity-major fp32 out, bias+relu.
// ---------------------------------------------------------------------------
extern __shared__ __align__(16) char dsm1[];
__global__ __launch_bounds__(256, 2) void deconv1_mma_k(const float* __restrict__ bias) {
    unsigned xh = smem_u32(dsm1);            // 64 * 264 * 2B = 33792
    int t = threadIdx.x;
    int mh = blockIdx.x, p = blockIdx.y, b = blockIdx.z;
    int ph = p >> 1, pw = p & 1;

    // ---- build X from packed fp16 ----
    {
        int n = t & 63, kq = t >> 6;         // thread: one n, 16 ci
        int r0 = mh - 1 + ph, c0 = n - 1 + pw;
        bool rok0 = ((unsigned)r0 < 64u), rok1 = ((unsigned)(r0 + 1) < 64u);
        bool cok0 = ((unsigned)c0 < 64u), cok1 = ((unsigned)(c0 + 1) < 64u);
        const unsigned* zb = g_zqc + (size_t)b * 262144 + (size_t)r0 * 64 + c0;
        unsigned rowoff = (unsigned)(n * 264) * 2;
        #pragma unroll 4
        for (int cc = 0; cc < 16; cc++) {
            int ci = kq * 16 + cc;
            const unsigned* zc = zb + (size_t)ci * 4096;
            unsigned w00 = (rok0 && cok0) ? __ldg(zc)      : 0u;
            unsigned w01 = (rok0 && cok1) ? __ldg(zc + 1)  : 0u;
            unsigned w10 = (rok1 && cok0) ? __ldg(zc + 64) : 0u;
            unsigned w11 = (rok1 && cok1) ? __ldg(zc + 65) : 0u;
            unsigned hp0 = prmt(w00, w01, 0x5410u);
            unsigned hp1 = prmt(w10, w11, 0x5410u);
            unsigned off = rowoff + (unsigned)(ci * 4) * 2;
            asm volatile("st.shared.b32 [%0], %1;" :: "r"(xh + off),     "r"(hp0) : "memory");
            asm volatile("st.shared.b32 [%0], %1;" :: "r"(xh + off + 4), "r"(hp1) : "memory");
        }
    }
    __syncthreads();

    // ---- warp MMA ----
    int wid = t >> 5, lane = t & 31;
    int g = lane >> 2, q4 = lane & 3;
    int m0 = (wid >> 1) * 32, n0 = (wid & 1) * 32;
    const __half* wh = g_w1h + (size_t)p * 32768;

    float c[2][4][4];
    #pragma unroll
    for (int mt = 0; mt < 2; mt++)
        #pragma unroll
        for (int nt = 0; nt < 4; nt++)
            #pragma unroll
            for (int j = 0; j < 4; j++) c[mt][nt][j] = 0.f;

    unsigned ah[2][4], ahn[2][4];
    #pragma unroll
    for (int mt = 0; mt < 2; mt++) {
        const __half* w0 = wh + (size_t)(m0 + mt * 16 + g) * 256 + 2 * q4;
        ah[mt][0] = __ldg((const unsigned*)w0);
        ah[mt][1] = __ldg((const unsigned*)(w0 + 2048));
        ah[mt][2] = __ldg((const unsigned*)(w0 + 8));
        ah[mt][3] = __ldg((const unsigned*)(w0 + 2056));
    }

    for (int kb = 0; kb < 16; kb++) {
        if (kb < 15) {
            int nkb = (kb + 1) * 16;
            #pragma unroll
            for (int mt = 0; mt < 2; mt++) {
                const __half* w0 = wh + (size_t)(m0 + mt * 16 + g) * 256 + nkb + 2 * q4;
                ahn[mt][0] = __ldg((const unsigned*)w0);
                ahn[mt][1] = __ldg((const unsigned*)(w0 + 2048));
                ahn[mt][2] = __ldg((const unsigned*)(w0 + 8));
                ahn[mt][3] = __ldg((const unsigned*)(w0 + 2056));
            }
        }
        unsigned bh[4][2];
        #pragma unroll
        for (int nt = 0; nt < 4; nt++) {
            unsigned boff = (unsigned)(((n0 + nt * 8 + g) * 264) + kb * 16 + 2 * q4) * 2;
            asm volatile("ld.shared.b32 %0, [%1];" : "=r"(bh[nt][0]) : "r"(xh + boff));
            asm volatile("ld.shared.b32 %0, [%1];" : "=r"(bh[nt][1]) : "r"(xh + boff + 16));
        }
        #pragma unroll
        for (int nt = 0; nt < 4; nt++)
            #pragma unroll
            for (int mt = 0; mt < 2; mt++)
                asm volatile(
                    "mma.sync.aligned.m16n8k16.row.col.f32.f16.f16.f32 "
                    "{%0,%1,%2,%3}, {%4,%5,%6,%7}, {%8,%9}, {%0,%1,%2,%3};"
                    : "+f"(c[mt][nt][0]), "+f"(c[mt][nt][1]),
                      "+f"(c[mt][nt][2]), "+f"(c[mt][nt][3])
                    : "r"(ah[mt][0]), "r"(ah[mt][1]), "r"(ah[mt][2]), "r"(ah[mt][3]),
                      "r"(bh[nt][0]), "r"(bh[nt][1]));
        #pragma unroll
        for (int mt = 0; mt < 2; mt++)
            #pragma unroll
            for (int j = 0; j < 4; j++) ah[mt][j] = ahn[mt][j];
    }

    // ---- epilogue: bias + relu, parity-major store ----
    float* dbase = g_d1 + ((size_t)(b * 4 + p) * 128) * 4096 + (size_t)mh * 64;
    #pragma unroll
    for (int mt = 0; mt < 2; mt++) {
        int co0 = m0 + mt * 16 + g;
        float bv0 = __ldg(bias + co0);
        float bv1 = __ldg(bias + co0 + 8);
        #pragma unroll
        for (int nt = 0; nt < 4; nt++) {
            int col = n0 + nt * 8 + 2 * q4;
            float2 o0, o1;
            o0.x = fmaxf(c[mt][nt][0] + bv0, 0.f);
            o0.y = fmaxf(c[mt][nt][1] + bv0, 0.f);
            o1.x = fmaxf(c[mt][nt][2] + bv1, 0.f);
            o1.y = fmaxf(c[mt][nt][3] + bv1, 0.f);
            *(float2*)(dbase + (size_t)co0 * 4096 + col)       = o0;
            *(float2*)(dbase + (size_t)(co0 + 8) * 4096 + col) = o1;
        }
    }
}

// ---------------------------------------------------------------------------
// deconv2 (FFMA2 tap-split, 2 outputs/thread): thread handles (ow, ow+16),
// same parity -> shared weights. Block tile 16(oh) x 32(ow); sX = 32ci x 10x18.
// Reads parity-major fp32 d1.
// ---------------------------------------------------------------------------
__global__ __launch_bounds__(256) void deconv2_k(const float* __restrict__ bias,
                                                 float* __restrict__ out) {
    __shared__ float sX[32 * 180];                       // 23 KB
    __shared__ __align__(16) float sW[32 * 4 * 3 * 4];
    int b = blockIdx.z, oht = blockIdx.y, owt = blockIdx.x;  // grid (8, 16, B)
    int t = threadIdx.x;
    int r0 = oht * 8 - 1, c0 = owt * 16 - 1;
    int oh_l = t >> 4, ow_l = t & 15;
    int ph = oh_l & 1, pw = ow_l & 1, p = ph * 2 + pw;
    int xr = (oh_l >> 1) + ph;
    int xc = (ow_l >> 1) + pw;
    ull a0A = 0ull, a1A = 0ull, a2A = 0ull;
    ull a0B = 0ull, a1B = 0ull, a2B = 0ull;
    unsigned swu = smem_u32(sW) + p * 48;
    for (int chn = 0; chn < 4; chn++) {
        __syncthreads();
        for (int i = t; i < 5760; i += 256) {
            int ci = i / 180, rem = i % 180;
            int rr = rem / 18, cc = rem % 18;
            int ih = r0 + rr, iw = c0 + cc;
            float v = 0.f;
            if ((unsigned)ih < 128u && (unsigned)iw < 128u) {
                int pq = (ih & 1) * 2 + (iw & 1);
                v = g_d1[((size_t)(b * 4 + pq) * 128 + (chn * 32 + ci)) * 4096
                         + (ih >> 1) * 64 + (iw >> 1)];
            }
            sX[i] = v;
        }
        for (int i = t; i < 384; i += 256) {
            int ci = i / 12, rem = i % 12;
            ((float4*)sW)[i] =
                ((const float4*)g_wr2)[(size_t)(chn * 32 + ci) * 12 + rem];
        }
        __syncthreads();
        #pragma unroll 4
        for (int ci = 0; ci < 32; ci++) {
            int base = ci * 180;
            ull XA0 = pk2ab(sX[base + xr * 18 + xc], sX[base + xr * 18 + xc + 1]);
            ull XB0 = pk2ab(sX[base + (xr + 1) * 18 + xc],
                            sX[base + (xr + 1) * 18 + xc + 1]);
            ull XA1 = pk2ab(sX[base + xr * 18 + xc + 8], sX[base + xr * 18 + xc + 9]);
            ull XB1 = pk2ab(sX[base + (xr + 1) * 18 + xc + 8],
                            sX[base + (xr + 1) * 18 + xc + 9]);
            unsigned a = swu + ci * 192;
            ull w01, w23, v01, v23, u01, u23;
            lds2(w01, w23, a);
            lds2(v01, v23, a + 16);
            lds2(u01, u23, a + 32);
            fma2(a0A, XA0, w01); fma2(a0A, XB0, w23);
            fma2(a1A, XA0, v01); fma2(a1A, XB0, v23);
            fma2(a2A, XA0, u01); fma2(a2A, XB0, u23);
            fma2(a0B, XA1, w01); fma2(a0B, XB1, w23);
            fma2(a1B, XA1, v01); fma2(a1B, XB1, v23);
            fma2(a2B, XA1, u01); fma2(a2B, XB1, u23);
        }
    }
    int oh = oht * 16 + oh_l, ow = owt * 32 + ow_l;
    size_t obase = (size_t)b * 3 * 65536 + (size_t)oh * 256 + ow;
    float lo, hi;
    float b0 = __ldg(bias + 0), b1 = __ldg(bias + 1), b2 = __ldg(bias + 2);
    upk2(lo, hi, a0A); out[obase]             = (lo + hi) + b0;
    upk2(lo, hi, a1A); out[obase + 65536]     = (lo + hi) + b1;
    upk2(lo, hi, a2A); out[obase + 2 * 65536] = (lo + hi) + b2;
    upk2(lo, hi, a0B); out[obase + 16]             = (lo + hi) + b0;
    upk2(lo, hi, a1B); out[obase + 65536 + 16]     = (lo + hi) + b1;
    upk2(lo, hi, a2B); out[obase + 2 * 65536 + 16] = (lo + hi) + b2;
}

// ---------------------------------------------------------------------------
extern "C" void kernel_launch(void* const* d_in, const int* in_sizes, int n_in,
                              void* d_out, int out_size) {
    const float* x      = (const float*)d_in[0];
    const float* enc_w1 = (const float*)d_in[1];
    const float* enc_b1 = (const float*)d_in[2];
    const float* enc_w2 = (const float*)d_in[3];
    const float* enc_b2 = (const float*)d_in[4];
    const float* dec_w1 = (const float*)d_in[5];
    const float* dec_b1 = (const float*)d_in[6];
    const float* dec_w2 = (const float*)d_in[7];
    const float* dec_b2 = (const float*)d_in[8];
    const float* cb     = (const float*)d_in[9];
    float* out = (float*)d_out;

    prep_k<<<64, 256>>>(cb, enc_w2, dec_w1, dec_w2);
    conv1_k<<<dim3(8, 8, BATCH), 256>>>(x, enc_w1, enc_b1);
    conv2_k<<<dim3(2, 8, BATCH), 256>>>(enc_b2);
    vq_k<<<512, 256>>>(cb);
    deconv1_mma_k<<<dim3(64, 4, BATCH), 256, 33792>>>(dec_b1);
    deconv2_k<<<dim3(8, 16, BATCH), 256>>>(dec_b2, out);
}